// round 9
// baseline (speedup 1.0000x reference)
#include <cuda_runtime.h>
#include <cstdint>

#define N_NODES   200000
#define N_EDGES   3200000
#define NUM_GRAPHS 512
#define NUM_FEAT  256
#define DH        16
#define KTOP      40
#define MAXS      4096
#define ROWCAP    64        // padded CSR row capacity; P(deg>64)~1e-21 for Poisson(16)

// packed f32x2 FMA (only reachable via PTX on sm_103a)
#define FMA2(d, a, b) asm("fma.rn.f32x2 %0, %1, %2, %0;" : "+l"(d) : "l"(a), "l"(b))

// ---------------- scratch (static device globals; no allocation) ----------------
// zero-initialized at load; sortpool epilogue re-zeroes g_cnt so every replay
// starts from identical state (deterministic).
__device__ float g_xw1[N_NODES * DH];       // x @ W1, then scaled by dinv
__device__ float g_xw2[N_NODES * DH];       // dinv[n] * (relu(h1) @ W2)
__device__ float g_h2 [N_NODES * DH];       // final node features
__device__ int   g_cnt[N_NODES];            // per-node degree / insert cursor
__device__ float g_dinv[N_NODES];
__device__ int   g_slot[N_NODES * ROWCAP];  // padded CSR rows (51.2 MB)

// ---------------- side stream for gemm overlap (host objects only) ----------------
static cudaStream_t g_side = nullptr;
static cudaEvent_t  g_evA = nullptr, g_evD = nullptr, g_evB = nullptr;
static bool g_ok = false;
struct SInit {
    SInit() {
        g_ok = (cudaStreamCreateWithFlags(&g_side, cudaStreamNonBlocking) == cudaSuccess) &&
               (cudaEventCreateWithFlags(&g_evA, cudaEventDisableTiming) == cudaSuccess) &&
               (cudaEventCreateWithFlags(&g_evD, cudaEventDisableTiming) == cudaSuccess) &&
               (cudaEventCreateWithFlags(&g_evB, cudaEventDisableTiming) == cudaSuccess);
    }
};
static SInit g_sinit;

// ---------------- single-pass padded-CSR insert (int2, exact tiles) ----------------
__global__ void insert_kernel(const int* __restrict__ ei) {
    int e2 = (blockIdx.x * blockDim.x + threadIdx.x) * 2;   // N_EDGES % 512 == 0
    int2 d = *reinterpret_cast<const int2*>(&ei[N_EDGES + e2]);
    int2 s = *reinterpret_cast<const int2*>(&ei[e2]);
    int p0 = atomicAdd(&g_cnt[d.x], 1);
    if (p0 < ROWCAP) g_slot[d.x * ROWCAP + p0] = s.x;
    int p1 = atomicAdd(&g_cnt[d.y], 1);
    if (p1 < ROWCAP) g_slot[d.y * ROWCAP + p1] = s.y;
}

// ---------------- GEMM: g_xw1 = x @ W1 (unscaled; dinv applied later) ----------------
__global__ __launch_bounds__(128) void gemm_kernel(const float* __restrict__ x,
                                                   const float* __restrict__ W1) {
    __shared__ float ws[NUM_FEAT * DH];  // 16 KB
    __shared__ float xs[32 * 129];       // ~16.5 KB, [k][row] padded
    int tid = threadIdx.x;
    int row0 = blockIdx.x * 128;
    for (int i = tid; i < NUM_FEAT * DH; i += 128) ws[i] = W1[i];

    unsigned long long acc2[8];
#pragma unroll
    for (int c = 0; c < 8; c++) acc2[c] = 0ull;

    for (int kc = 0; kc < 8; kc++) {
        __syncthreads();
#pragma unroll
        for (int it = 0; it < 8; it++) {
            int lin = it * 128 + tid;
            int r = lin >> 3, j4 = lin & 7;
            int row = row0 + r;
            float4 v = make_float4(0.f, 0.f, 0.f, 0.f);
            if (row < N_NODES)
                v = reinterpret_cast<const float4*>(x)[row * 64 + kc * 8 + j4];
            int kk = j4 * 4;
            xs[(kk + 0) * 129 + r] = v.x;
            xs[(kk + 1) * 129 + r] = v.y;
            xs[(kk + 2) * 129 + r] = v.z;
            xs[(kk + 3) * 129 + r] = v.w;
        }
        __syncthreads();
        const float* wc = ws + kc * 32 * 16;
#pragma unroll
        for (int k = 0; k < 32; k++) {
            float xa = xs[k * 129 + tid];
            unsigned long long xx;
            asm("mov.b64 %0, {%1, %1};" : "=l"(xx) : "f"(xa));
            const ulonglong2* wr = reinterpret_cast<const ulonglong2*>(wc + k * 16);
            ulonglong2 w01 = wr[0], w23 = wr[1], w45 = wr[2], w67 = wr[3];
            FMA2(acc2[0], xx, w01.x);
            FMA2(acc2[1], xx, w01.y);
            FMA2(acc2[2], xx, w23.x);
            FMA2(acc2[3], xx, w23.y);
            FMA2(acc2[4], xx, w45.x);
            FMA2(acc2[5], xx, w45.y);
            FMA2(acc2[6], xx, w67.x);
            FMA2(acc2[7], xx, w67.y);
        }
    }
    int row = row0 + tid;
    if (row < N_NODES) {
        float r[16];
#pragma unroll
        for (int c = 0; c < 8; c++)
            asm("mov.b64 {%0, %1}, %2;" : "=f"(r[2 * c]), "=f"(r[2 * c + 1]) : "l"(acc2[c]));
        float4* o = reinterpret_cast<float4*>(&g_xw1[row * 16]);
        o[0] = make_float4(r[0],  r[1],  r[2],  r[3]);
        o[1] = make_float4(r[4],  r[5],  r[6],  r[7]);
        o[2] = make_float4(r[8],  r[9],  r[10], r[11]);
        o[3] = make_float4(r[12], r[13], r[14], r[15]);
    }
}

// ---------------- scale: g_xw1 *= dinv, also materializes g_dinv ----------------
// runs on side stream after insert (needs final g_cnt) and gemm.
__global__ __launch_bounds__(256) void scale_kernel() {
    int i = blockIdx.x * blockDim.x + threadIdx.x;   // one float4 per thread; 800000 exact
    int n = i >> 2;
    float dn = rsqrtf((float)(g_cnt[n] + 1));        // +1 self loop
    if ((i & 3) == 0) g_dinv[n] = dn;
    float4 v = reinterpret_cast<float4*>(g_xw1)[i];
    v.x *= dn; v.y *= dn; v.z *= dn; v.w *= dn;
    reinterpret_cast<float4*>(g_xw1)[i] = v;
}

// ---------------- conv1: aggregate -> relu(+b1) -> @W2 -> dinv* -> g_xw2 ----------------
// 4 threads per node, float4 per thread. Inputs pre-scaled by dinv (self loop folds in).
__global__ __launch_bounds__(256) void conv1_kernel(const float* __restrict__ b1,
                                                    const float* __restrict__ W2) {
    __shared__ float4 w2s[64];
    __shared__ float hs[64][17];
    int tid = threadIdx.x;
    if (tid < 64) w2s[tid] = reinterpret_cast<const float4*>(W2)[tid];
    int local = tid >> 2, q = tid & 3;
    int n = blockIdx.x * 64 + local;
    float dn = 0.f;
    float hx = 0.f, hy = 0.f, hz = 0.f, hw = 0.f;
    if (n < N_NODES) {
        dn = g_dinv[n];
        const float4* tbl = reinterpret_cast<const float4*>(g_xw1);
        float4 acc = tbl[n * 4 + q];      // self loop (pre-scaled)
        int deg = g_cnt[n];
        if (deg > ROWCAP) deg = ROWCAP;
        const int* row = g_slot + n * ROWCAP;
        int j = 0;
        for (; j + 1 < deg; j += 2) {
            int s0 = row[j], s1 = row[j + 1];
            float4 a = tbl[s0 * 4 + q];
            float4 b = tbl[s1 * 4 + q];
            acc.x += a.x + b.x; acc.y += a.y + b.y;
            acc.z += a.z + b.z; acc.w += a.w + b.w;
        }
        if (j < deg) {
            int s = row[j];
            float4 a = tbl[s * 4 + q];
            acc.x += a.x; acc.y += a.y; acc.z += a.z; acc.w += a.w;
        }
        float4 bq = reinterpret_cast<const float4*>(b1)[q];
        hx = fmaxf(fmaf(acc.x, dn, bq.x), 0.f);
        hy = fmaxf(fmaf(acc.y, dn, bq.y), 0.f);
        hz = fmaxf(fmaf(acc.z, dn, bq.z), 0.f);
        hw = fmaxf(fmaf(acc.w, dn, bq.w), 0.f);
    }
    hs[local][q * 4 + 0] = hx;
    hs[local][q * 4 + 1] = hy;
    hs[local][q * 4 + 2] = hz;
    hs[local][q * 4 + 3] = hw;
    __syncthreads();
    if (n < N_NODES) {
        float4 o = make_float4(0.f, 0.f, 0.f, 0.f);
#pragma unroll
        for (int k = 0; k < 16; k++) {
            float hk = hs[local][k];
            float4 w = w2s[k * 4 + q];
            o.x = fmaf(hk, w.x, o.x);
            o.y = fmaf(hk, w.y, o.y);
            o.z = fmaf(hk, w.z, o.z);
            o.w = fmaf(hk, w.w, o.w);
        }
        reinterpret_cast<float4*>(g_xw2)[n * 4 + q] =
            make_float4(o.x * dn, o.y * dn, o.z * dn, o.w * dn);
    }
}

// ---------------- conv2: aggregate -> relu(+b2) -> g_h2 ----------------
__global__ __launch_bounds__(256) void conv2_kernel(const float* __restrict__ b2) {
    int tid = threadIdx.x;
    int local = tid >> 2, q = tid & 3;
    int n = blockIdx.x * 64 + local;
    if (n >= N_NODES) return;
    float dn = g_dinv[n];
    const float4* tbl = reinterpret_cast<const float4*>(g_xw2);
    float4 acc = tbl[n * 4 + q];
    int deg = g_cnt[n];
    if (deg > ROWCAP) deg = ROWCAP;
    const int* row = g_slot + n * ROWCAP;
    int j = 0;
    for (; j + 1 < deg; j += 2) {
        int s0 = row[j], s1 = row[j + 1];
        float4 a = tbl[s0 * 4 + q];
        float4 b = tbl[s1 * 4 + q];
        acc.x += a.x + b.x; acc.y += a.y + b.y;
        acc.z += a.z + b.z; acc.w += a.w + b.w;
    }
    if (j < deg) {
        int s = row[j];
        float4 a = tbl[s * 4 + q];
        acc.x += a.x; acc.y += a.y; acc.z += a.z; acc.w += a.w;
    }
    float4 bq = reinterpret_cast<const float4*>(b2)[q];
    float4 h;
    h.x = fmaxf(fmaf(acc.x, dn, bq.x), 0.f);
    h.y = fmaxf(fmaf(acc.y, dn, bq.y), 0.f);
    h.z = fmaxf(fmaf(acc.z, dn, bq.z), 0.f);
    h.w = fmaxf(fmaf(acc.w, dn, bq.w), 0.f);
    reinterpret_cast<float4*>(g_h2)[n * 4 + q] = h;
}

// ---------------- sort pool + fc + state reset: one block per graph ----------------
__global__ __launch_bounds__(256) void sortpool_kernel(const int* __restrict__ batch,
                                                       const float* __restrict__ fc_w,
                                                       const float* __restrict__ fc_b,
                                                       float* __restrict__ out) {
    __shared__ unsigned long long keys[MAXS];
    __shared__ float red[256];
    __shared__ int sh_bounds[2];
    int g = blockIdx.x;
    int tid = threadIdx.x;
    if (tid < 2) {
        int target = g + tid;
        int lo = 0, hi = N_NODES;
        while (lo < hi) {
            int mid = (lo + hi) >> 1;
            if (batch[mid] < target) lo = mid + 1; else hi = mid;
        }
        sh_bounds[tid] = lo;
    }

    // epilogue duty: re-zero g_cnt for the NEXT execution (deterministic:
    // globals start zeroed; every execution leaves them zeroed again).
    {
        int chunk = (N_NODES + NUM_GRAPHS - 1) / NUM_GRAPHS;      // 391
        int s = g * chunk;
        int e = s + chunk; if (e > N_NODES) e = N_NODES;
        for (int i = s + tid; i < e; i += 256) g_cnt[i] = 0;
    }
    __syncthreads();
    int s0 = sh_bounds[0], s1 = sh_bounds[1];
    int cnt = s1 - s0;
    if (cnt > MAXS) cnt = MAXS;
    int M = 1;
    while (M < cnt) M <<= 1;

    for (int i = tid; i < M; i += 256) {
        unsigned long long kk;
        if (i < cnt) {
            float v = g_h2[(s0 + i) * 16 + 15];       // v >= 0 post-relu
            unsigned vb = __float_as_uint(v);
            kk = ((unsigned long long)(0xFFFFFFFFu - vb) << 32) | (unsigned)i;
        } else {
            kk = 0xFFFFFFFFFFFFFFFFull;
        }
        keys[i] = kk;
    }
    __syncthreads();

    for (int len = 2; len <= M; len <<= 1) {
        for (int j = len >> 1; j > 0; j >>= 1) {
            for (int i = tid; i < M; i += 256) {
                int ixj = i ^ j;
                if (ixj > i) {
                    unsigned long long a = keys[i], b = keys[ixj];
                    bool up = ((i & len) == 0);
                    if ((a > b) == up) { keys[i] = b; keys[ixj] = a; }
                }
            }
            __syncthreads();
        }
    }

    int kl = (cnt < KTOP) ? cnt : KTOP;
    float part = 0.f;
    for (int t = tid; t < KTOP * 16; t += 256) {
        int r = t >> 4, f = t & 15;
        if (r < kl) {
            int li = (int)(keys[r] & 0xFFFFFFFFull);
            part = fmaf(g_h2[(s0 + li) * 16 + f], fc_w[t], part);
        }
    }
    red[tid] = part;
    __syncthreads();
    for (int s = 128; s > 0; s >>= 1) {
        if (tid < s) red[tid] += red[tid + s];
        __syncthreads();
    }
    if (tid == 0) out[g] = red[0] + fc_b[0];
}

// ---------------- launch ----------------
extern "C" void kernel_launch(void* const* d_in, const int* in_sizes, int n_in,
                              void* d_out, int out_size) {
    const float* x     = (const float*)d_in[0];
    const int*   ei    = (const int*)  d_in[1];
    const int*   batch = (const int*)  d_in[2];
    // d_in[3] edge_weight: unused by reference forward
    const float* W1    = (const float*)d_in[4];
    const float* b1    = (const float*)d_in[5];
    const float* W2    = (const float*)d_in[6];
    const float* b2    = (const float*)d_in[7];
    const float* fc_w  = (const float*)d_in[8];
    const float* fc_b  = (const float*)d_in[9];
    float* out = (float*)d_out;

    const int EBLK2 = N_EDGES / 2 / 256;           // 6250 (exact)
    const int CBLK  = (N_NODES + 63) / 64;         // 3125
    const int GBLK  = (N_NODES + 127) / 128;       // 1563
    const int SBLK  = N_NODES * 4 / 256;           // 3125 (exact)

    if (g_ok) {
        // fork: gemm runs on side stream concurrently with the CSR insert
        cudaEventRecord(g_evA, 0);
        cudaStreamWaitEvent(g_side, g_evA, 0);
        gemm_kernel<<<GBLK, 128, 0, g_side>>>(x, W1);

        insert_kernel<<<EBLK2, 256>>>(ei);          // single-pass padded CSR
        cudaEventRecord(g_evD, 0);                  // g_cnt/g_slot ready

        cudaStreamWaitEvent(g_side, g_evD, 0);
        scale_kernel<<<SBLK, 256, 0, g_side>>>();   // xw1 *= dinv, writes g_dinv
        cudaEventRecord(g_evB, g_side);
        cudaStreamWaitEvent(0, g_evB, 0);

        conv1_kernel<<<CBLK, 256>>>(b1, W2);
        conv2_kernel<<<CBLK, 256>>>(b2);
        sortpool_kernel<<<NUM_GRAPHS, 256>>>(batch, fc_w, fc_b, out);
    } else {
        // serial fallback
        insert_kernel<<<EBLK2, 256>>>(ei);
        gemm_kernel <<<GBLK, 128>>>(x, W1);
        scale_kernel<<<SBLK, 256>>>();
        conv1_kernel<<<CBLK, 256>>>(b1, W2);
        conv2_kernel<<<CBLK, 256>>>(b2);
        sortpool_kernel<<<NUM_GRAPHS, 256>>>(batch, fc_w, fc_b, out);
    }
}

// round 10
// speedup vs baseline: 1.0087x; 1.0087x over previous
#include <cuda_runtime.h>
#include <cstdint>

#define N_NODES   200000
#define N_EDGES   3200000
#define NUM_GRAPHS 512
#define NUM_FEAT  256
#define DH        16
#define KTOP      40
#define MAXS      4096
#define SCAN_TILE 1024
#define NB_SCAN   ((N_NODES + SCAN_TILE - 1) / SCAN_TILE)   // 196

// packed f32x2 FMA (only reachable via PTX on sm_103a)
#define FMA2(d, a, b) asm("fma.rn.f32x2 %0, %1, %2, %0;" : "+l"(d) : "l"(a), "l"(b))

// ---------------- scratch (static device globals; no allocation) ----------------
__device__ float g_xw1[N_NODES * DH];   // x @ W1, then scaled by dinv
__device__ float g_xw2[N_NODES * DH];   // dinv[n] * (relu(h1) @ W2)
__device__ float g_h2 [N_NODES * DH];   // final node features
__device__ int   g_deg[N_NODES];
__device__ float g_dinv[N_NODES];
__device__ int   g_off[N_NODES + 1];
__device__ int   g_epos[N_EDGES];       // slot of edge within its dst row (from hist)
__device__ int   g_bsums[256];
__device__ int   g_csr[N_EDGES];

// ---------------- side stream for gemm overlap (host objects only) ----------------
static cudaStream_t g_side = nullptr;
static cudaEvent_t  g_evA = nullptr, g_evD = nullptr, g_evB = nullptr;
static bool g_ok = false;
struct SInit {
    SInit() {
        g_ok = (cudaStreamCreateWithFlags(&g_side, cudaStreamNonBlocking) == cudaSuccess) &&
               (cudaEventCreateWithFlags(&g_evA, cudaEventDisableTiming) == cudaSuccess) &&
               (cudaEventCreateWithFlags(&g_evD, cudaEventDisableTiming) == cudaSuccess) &&
               (cudaEventCreateWithFlags(&g_evB, cudaEventDisableTiming) == cudaSuccess);
    }
};
static SInit g_sinit;

// ---------------- histogram of dst (int2); persists slot positions ----------------
__global__ void hist_kernel(const int* __restrict__ ei) {
    int e2 = (blockIdx.x * blockDim.x + threadIdx.x) * 2;
    if (e2 + 1 < N_EDGES) {
        int2 d = *reinterpret_cast<const int2*>(&ei[N_EDGES + e2]);
        int2 p;
        p.x = atomicAdd(&g_deg[d.x], 1);
        p.y = atomicAdd(&g_deg[d.y], 1);
        *reinterpret_cast<int2*>(&g_epos[e2]) = p;
    } else if (e2 < N_EDGES) {
        g_epos[e2] = atomicAdd(&g_deg[ei[N_EDGES + e2]], 1);
    }
}

// ---------------- scan phase 1 (also computes dinv) ----------------
__global__ __launch_bounds__(256) void scan1_kernel() {
    __shared__ int warp_tot[8];
    int tid = threadIdx.x, lane = tid & 31, wid = tid >> 5;
    int base = blockIdx.x * SCAN_TILE + tid * 4;
    int v[4]; int s = 0;
#pragma unroll
    for (int i = 0; i < 4; i++) {
        int idx = base + i;
        v[i] = (idx < N_NODES) ? g_deg[idx] : 0;
        s += v[i];
        if (idx < N_NODES) g_dinv[idx] = rsqrtf((float)(v[i] + 1));  // +1 self loop
    }
    int inc = s;
#pragma unroll
    for (int d = 1; d < 32; d <<= 1) {
        int t = __shfl_up_sync(0xFFFFFFFFu, inc, d);
        if (lane >= d) inc += t;
    }
    if (lane == 31) warp_tot[wid] = inc;
    __syncthreads();
    if (wid == 0) {
        int w = (lane < 8) ? warp_tot[lane] : 0;
#pragma unroll
        for (int d = 1; d < 8; d <<= 1) {
            int t = __shfl_up_sync(0xFFFFFFFFu, w, d);
            if (lane >= d) w += t;
        }
        if (lane < 8) warp_tot[lane] = w;
    }
    __syncthreads();
    int wex = (wid > 0) ? warp_tot[wid - 1] : 0;
    int run = wex + inc - s;
#pragma unroll
    for (int i = 0; i < 4; i++) {
        int idx = base + i;
        if (idx < N_NODES) g_off[idx] = run;
        run += v[i];
    }
    if (tid == blockDim.x - 1) g_bsums[blockIdx.x] = warp_tot[7];
}

// ---------------- scan phase 2 (shuffle-based, 196 values) ----------------
__global__ void scan2_kernel() {
    __shared__ int wsum[8];
    int t = threadIdx.x, lane = t & 31, w = t >> 5;
    int v = (t < NB_SCAN) ? g_bsums[t] : 0;
    int inc = v;
#pragma unroll
    for (int d = 1; d < 32; d <<= 1) {
        int x = __shfl_up_sync(0xFFFFFFFFu, inc, d);
        if (lane >= d) inc += x;
    }
    if (lane == 31) wsum[w] = inc;
    __syncthreads();
    if (w == 0) {
        int s = (lane < 8) ? wsum[lane] : 0;
#pragma unroll
        for (int d = 1; d < 8; d <<= 1) {
            int x = __shfl_up_sync(0xFFFFFFFFu, s, d);
            if (lane >= d) s += x;
        }
        if (lane < 8) wsum[lane] = s;
    }
    __syncthreads();
    int wex = (w > 0) ? wsum[w - 1] : 0;
    if (t < NB_SCAN) g_bsums[t] = wex + inc - v;  // exclusive
}

// ---------------- scan phase 3 (finalize g_off) ----------------
__global__ void scan3_kernel() {
    int bs = g_bsums[blockIdx.x];
    int base = blockIdx.x * SCAN_TILE + threadIdx.x * 4;
#pragma unroll
    for (int i = 0; i < 4; i++) {
        int idx = base + i;
        if (idx < N_NODES) g_off[idx] += bs;
    }
    if (blockIdx.x == 0 && threadIdx.x == 0) g_off[N_NODES] = N_EDGES;
}

// ---------------- CSR fill (atomic-free: slot from hist, offset from scan) ---------
__global__ void fill_kernel(const int* __restrict__ ei) {
    int e2 = (blockIdx.x * blockDim.x + threadIdx.x) * 2;
    if (e2 + 1 < N_EDGES) {
        int2 d = *reinterpret_cast<const int2*>(&ei[N_EDGES + e2]);
        int2 s = *reinterpret_cast<const int2*>(&ei[e2]);
        int2 p = *reinterpret_cast<const int2*>(&g_epos[e2]);
        g_csr[g_off[d.x] + p.x] = s.x;
        g_csr[g_off[d.y] + p.y] = s.y;
    } else if (e2 < N_EDGES) {
        int d = ei[N_EDGES + e2];
        g_csr[g_off[d] + g_epos[e2]] = ei[e2];
    }
}

// ---------------- GEMM: g_xw1 = x @ W1 (unscaled; dinv applied later) ----------------
__global__ __launch_bounds__(128) void gemm_kernel(const float* __restrict__ x,
                                                   const float* __restrict__ W1) {
    __shared__ float ws[NUM_FEAT * DH];  // 16 KB
    __shared__ float xs[32 * 129];       // ~16.5 KB, [k][row] padded
    int tid = threadIdx.x;
    int row0 = blockIdx.x * 128;
    for (int i = tid; i < NUM_FEAT * DH; i += 128) ws[i] = W1[i];

    unsigned long long acc2[8];
#pragma unroll
    for (int c = 0; c < 8; c++) acc2[c] = 0ull;

    for (int kc = 0; kc < 8; kc++) {
        __syncthreads();
#pragma unroll
        for (int it = 0; it < 8; it++) {
            int lin = it * 128 + tid;
            int r = lin >> 3, j4 = lin & 7;
            int row = row0 + r;
            float4 v = make_float4(0.f, 0.f, 0.f, 0.f);
            if (row < N_NODES)
                v = reinterpret_cast<const float4*>(x)[row * 64 + kc * 8 + j4];
            int kk = j4 * 4;
            xs[(kk + 0) * 129 + r] = v.x;
            xs[(kk + 1) * 129 + r] = v.y;
            xs[(kk + 2) * 129 + r] = v.z;
            xs[(kk + 3) * 129 + r] = v.w;
        }
        __syncthreads();
        const float* wc = ws + kc * 32 * 16;
#pragma unroll
        for (int k = 0; k < 32; k++) {
            float xa = xs[k * 129 + tid];
            unsigned long long xx;
            asm("mov.b64 %0, {%1, %1};" : "=l"(xx) : "f"(xa));
            const ulonglong2* wr = reinterpret_cast<const ulonglong2*>(wc + k * 16);
            ulonglong2 w01 = wr[0], w23 = wr[1], w45 = wr[2], w67 = wr[3];
            FMA2(acc2[0], xx, w01.x);
            FMA2(acc2[1], xx, w01.y);
            FMA2(acc2[2], xx, w23.x);
            FMA2(acc2[3], xx, w23.y);
            FMA2(acc2[4], xx, w45.x);
            FMA2(acc2[5], xx, w45.y);
            FMA2(acc2[6], xx, w67.x);
            FMA2(acc2[7], xx, w67.y);
        }
    }
    int row = row0 + tid;
    if (row < N_NODES) {
        float r[16];
#pragma unroll
        for (int c = 0; c < 8; c++)
            asm("mov.b64 {%0, %1}, %2;" : "=f"(r[2 * c]), "=f"(r[2 * c + 1]) : "l"(acc2[c]));
        float4* o = reinterpret_cast<float4*>(&g_xw1[row * 16]);
        o[0] = make_float4(r[0],  r[1],  r[2],  r[3]);
        o[1] = make_float4(r[4],  r[5],  r[6],  r[7]);
        o[2] = make_float4(r[8],  r[9],  r[10], r[11]);
        o[3] = make_float4(r[12], r[13], r[14], r[15]);
    }
}

// ---------------- scale: g_xw1 *= dinv (row-wise) ----------------
__global__ __launch_bounds__(256) void scale_kernel() {
    int i = blockIdx.x * blockDim.x + threadIdx.x;   // one float4 per thread
    if (i < N_NODES * 4) {
        float dn = g_dinv[i >> 2];
        float4 v = reinterpret_cast<float4*>(g_xw1)[i];
        v.x *= dn; v.y *= dn; v.z *= dn; v.w *= dn;
        reinterpret_cast<float4*>(g_xw1)[i] = v;
    }
}

// ---------------- conv1: aggregate -> relu(+b1) -> @W2 -> dinv* -> g_xw2 ----------------
// 4 threads per node, float4 per thread. Inputs pre-scaled by dinv (self loop folds in).
__global__ __launch_bounds__(256) void conv1_kernel(const float* __restrict__ b1,
                                                    const float* __restrict__ W2) {
    __shared__ float4 w2s[64];
    __shared__ float hs[64][17];
    int tid = threadIdx.x;
    if (tid < 64) w2s[tid] = reinterpret_cast<const float4*>(W2)[tid];
    int local = tid >> 2, q = tid & 3;
    int n = blockIdx.x * 64 + local;
    float dn = 0.f;
    float hx = 0.f, hy = 0.f, hz = 0.f, hw = 0.f;
    if (n < N_NODES) {
        dn = g_dinv[n];
        const float4* tbl = reinterpret_cast<const float4*>(g_xw1);
        float4 acc = tbl[n * 4 + q];      // self loop (pre-scaled)
        int e0 = g_off[n], e1 = g_off[n + 1];
        int j = e0;
        for (; j + 1 < e1; j += 2) {
            int s0 = g_csr[j], s1 = g_csr[j + 1];
            float4 a = tbl[s0 * 4 + q];
            float4 b = tbl[s1 * 4 + q];
            acc.x += a.x + b.x; acc.y += a.y + b.y;
            acc.z += a.z + b.z; acc.w += a.w + b.w;
        }
        if (j < e1) {
            int s = g_csr[j];
            float4 a = tbl[s * 4 + q];
            acc.x += a.x; acc.y += a.y; acc.z += a.z; acc.w += a.w;
        }
        float4 bq = reinterpret_cast<const float4*>(b1)[q];
        hx = fmaxf(fmaf(acc.x, dn, bq.x), 0.f);
        hy = fmaxf(fmaf(acc.y, dn, bq.y), 0.f);
        hz = fmaxf(fmaf(acc.z, dn, bq.z), 0.f);
        hw = fmaxf(fmaf(acc.w, dn, bq.w), 0.f);
    }
    hs[local][q * 4 + 0] = hx;
    hs[local][q * 4 + 1] = hy;
    hs[local][q * 4 + 2] = hz;
    hs[local][q * 4 + 3] = hw;
    __syncthreads();
    if (n < N_NODES) {
        float4 o = make_float4(0.f, 0.f, 0.f, 0.f);
#pragma unroll
        for (int k = 0; k < 16; k++) {
            float hk = hs[local][k];
            float4 w = w2s[k * 4 + q];
            o.x = fmaf(hk, w.x, o.x);
            o.y = fmaf(hk, w.y, o.y);
            o.z = fmaf(hk, w.z, o.z);
            o.w = fmaf(hk, w.w, o.w);
        }
        reinterpret_cast<float4*>(g_xw2)[n * 4 + q] =
            make_float4(o.x * dn, o.y * dn, o.z * dn, o.w * dn);
    }
}

// ---------------- conv2: aggregate -> relu(+b2) -> g_h2 ----------------
__global__ __launch_bounds__(256) void conv2_kernel(const float* __restrict__ b2) {
    int tid = threadIdx.x;
    int local = tid >> 2, q = tid & 3;
    int n = blockIdx.x * 64 + local;
    if (n >= N_NODES) return;
    float dn = g_dinv[n];
    const float4* tbl = reinterpret_cast<const float4*>(g_xw2);
    float4 acc = tbl[n * 4 + q];
    int e0 = g_off[n], e1 = g_off[n + 1];
    int j = e0;
    for (; j + 1 < e1; j += 2) {
        int s0 = g_csr[j], s1 = g_csr[j + 1];
        float4 a = tbl[s0 * 4 + q];
        float4 b = tbl[s1 * 4 + q];
        acc.x += a.x + b.x; acc.y += a.y + b.y;
        acc.z += a.z + b.z; acc.w += a.w + b.w;
    }
    if (j < e1) {
        int s = g_csr[j];
        float4 a = tbl[s * 4 + q];
        acc.x += a.x; acc.y += a.y; acc.z += a.z; acc.w += a.w;
    }
    float4 bq = reinterpret_cast<const float4*>(b2)[q];
    float4 h;
    h.x = fmaxf(fmaf(acc.x, dn, bq.x), 0.f);
    h.y = fmaxf(fmaf(acc.y, dn, bq.y), 0.f);
    h.z = fmaxf(fmaf(acc.z, dn, bq.z), 0.f);
    h.w = fmaxf(fmaf(acc.w, dn, bq.w), 0.f);
    reinterpret_cast<float4*>(g_h2)[n * 4 + q] = h;
}

// ---------------- sort pool + fc: one block per graph (self-locating) ----------------
__global__ __launch_bounds__(256) void sortpool_kernel(const int* __restrict__ batch,
                                                       const float* __restrict__ fc_w,
                                                       const float* __restrict__ fc_b,
                                                       float* __restrict__ out) {
    __shared__ unsigned long long keys[MAXS];
    __shared__ float red[256];
    __shared__ int sh_bounds[2];
    int g = blockIdx.x;
    int tid = threadIdx.x;
    if (tid < 2) {
        int target = g + tid;
        int lo = 0, hi = N_NODES;
        while (lo < hi) {
            int mid = (lo + hi) >> 1;
            if (batch[mid] < target) lo = mid + 1; else hi = mid;
        }
        sh_bounds[tid] = lo;
    }
    __syncthreads();
    int s0 = sh_bounds[0], s1 = sh_bounds[1];
    int cnt = s1 - s0;
    if (cnt > MAXS) cnt = MAXS;
    int M = 1;
    while (M < cnt) M <<= 1;

    for (int i = tid; i < M; i += 256) {
        unsigned long long kk;
        if (i < cnt) {
            float v = g_h2[(s0 + i) * 16 + 15];       // v >= 0 post-relu
            unsigned vb = __float_as_uint(v);
            kk = ((unsigned long long)(0xFFFFFFFFu - vb) << 32) | (unsigned)i;
        } else {
            kk = 0xFFFFFFFFFFFFFFFFull;
        }
        keys[i] = kk;
    }
    __syncthreads();

    for (int len = 2; len <= M; len <<= 1) {
        for (int j = len >> 1; j > 0; j >>= 1) {
            for (int i = tid; i < M; i += 256) {
                int ixj = i ^ j;
                if (ixj > i) {
                    unsigned long long a = keys[i], b = keys[ixj];
                    bool up = ((i & len) == 0);
                    if ((a > b) == up) { keys[i] = b; keys[ixj] = a; }
                }
            }
            __syncthreads();
        }
    }

    int kl = (cnt < KTOP) ? cnt : KTOP;
    float part = 0.f;
    for (int t = tid; t < KTOP * 16; t += 256) {
        int r = t >> 4, f = t & 15;
        if (r < kl) {
            int li = (int)(keys[r] & 0xFFFFFFFFull);
            part = fmaf(g_h2[(s0 + li) * 16 + f], fc_w[t], part);
        }
    }
    red[tid] = part;
    __syncthreads();
    for (int s = 128; s > 0; s >>= 1) {
        if (tid < s) red[tid] += red[tid + s];
        __syncthreads();
    }
    if (tid == 0) out[g] = red[0] + fc_b[0];
}

// ---------------- launch ----------------
extern "C" void kernel_launch(void* const* d_in, const int* in_sizes, int n_in,
                              void* d_out, int out_size) {
    const float* x     = (const float*)d_in[0];
    const int*   ei    = (const int*)  d_in[1];
    const int*   batch = (const int*)  d_in[2];
    // d_in[3] edge_weight: unused by reference forward
    const float* W1    = (const float*)d_in[4];
    const float* b1    = (const float*)d_in[5];
    const float* W2    = (const float*)d_in[6];
    const float* b2    = (const float*)d_in[7];
    const float* fc_w  = (const float*)d_in[8];
    const float* fc_b  = (const float*)d_in[9];
    float* out = (float*)d_out;

    const int EBLK2 = (N_EDGES / 2 + 255) / 256;   // 6250
    const int CBLK  = (N_NODES + 63) / 64;         // 3125
    const int GBLK  = (N_NODES + 127) / 128;       // 1563
    const int SBLK  = (N_NODES * 4 + 255) / 256;   // 3125

    void* p_deg = nullptr;
    cudaGetSymbolAddress(&p_deg, g_deg);

    if (g_ok) {
        // fork: gemm runs on side stream concurrently with CSR build
        cudaEventRecord(g_evA, 0);
        cudaStreamWaitEvent(g_side, g_evA, 0);
        gemm_kernel<<<GBLK, 128, 0, g_side>>>(x, W1);

        cudaMemsetAsync(p_deg, 0, N_NODES * sizeof(int), 0);
        hist_kernel <<<EBLK2, 256>>>(ei);
        scan1_kernel<<<NB_SCAN, 256>>>();
        cudaEventRecord(g_evD, 0);                  // dinv ready
        scan2_kernel<<<1, 256>>>();
        scan3_kernel<<<NB_SCAN, 256>>>();
        fill_kernel <<<EBLK2, 256>>>(ei);

        cudaStreamWaitEvent(g_side, g_evD, 0);
        scale_kernel<<<SBLK, 256, 0, g_side>>>();   // xw1 *= dinv
        cudaEventRecord(g_evB, g_side);
        cudaStreamWaitEvent(0, g_evB, 0);

        conv1_kernel<<<CBLK, 256>>>(b1, W2);
        conv2_kernel<<<CBLK, 256>>>(b2);
        sortpool_kernel<<<NUM_GRAPHS, 256>>>(batch, fc_w, fc_b, out);
    } else {
        // serial fallback
        cudaMemsetAsync(p_deg, 0, N_NODES * sizeof(int), 0);
        hist_kernel <<<EBLK2, 256>>>(ei);
        scan1_kernel<<<NB_SCAN, 256>>>();
        scan2_kernel<<<1, 256>>>();
        scan3_kernel<<<NB_SCAN, 256>>>();
        fill_kernel <<<EBLK2, 256>>>(ei);
        gemm_kernel <<<GBLK, 128>>>(x, W1);
        scale_kernel<<<SBLK, 256>>>();
        conv1_kernel<<<CBLK, 256>>>(b1, W2);
        conv2_kernel<<<CBLK, 256>>>(b2);
        sortpool_kernel<<<NUM_GRAPHS, 256>>>(batch, fc_w, fc_b, out);
    }
}

// round 11
// speedup vs baseline: 1.1106x; 1.1010x over previous
#include <cuda_runtime.h>
#include <cstdint>

#define N_NODES   200000
#define N_EDGES   3200000
#define NUM_GRAPHS 512
#define NUM_FEAT  256
#define DH        16
#define KTOP      40
#define MAXS      4096
#define SCAN_TILE 1024
#define NB_SCAN   ((N_NODES + SCAN_TILE - 1) / SCAN_TILE)   // 196

// packed f32x2 FMA (only reachable via PTX on sm_103a)
#define FMA2(d, a, b) asm("fma.rn.f32x2 %0, %1, %2, %0;" : "+l"(d) : "l"(a), "l"(b))

// ---------------- scratch (static device globals; no allocation) ----------------
__device__ float g_xw1[N_NODES * DH];   // x @ W1, then scaled by dinv
__device__ float g_xw2[N_NODES * DH];   // dinv[n] * (relu(h1) @ W2)
__device__ float g_h2 [N_NODES * DH];   // final node features
__device__ int   g_deg[N_NODES];
__device__ float g_dinv[N_NODES];
__device__ int   g_off[N_NODES + 1];
__device__ int   g_cur[N_NODES];        // absolute write cursor for fill
__device__ int   g_bsums[256];
__device__ int   g_csr[N_EDGES];

// ---------------- side stream for gemm overlap (host objects only) ----------------
static cudaStream_t g_side = nullptr;
static cudaEvent_t  g_evA = nullptr, g_evD = nullptr, g_evB = nullptr;
static bool g_ok = false;
struct SInit {
    SInit() {
        g_ok = (cudaStreamCreateWithFlags(&g_side, cudaStreamNonBlocking) == cudaSuccess) &&
               (cudaEventCreateWithFlags(&g_evA, cudaEventDisableTiming) == cudaSuccess) &&
               (cudaEventCreateWithFlags(&g_evD, cudaEventDisableTiming) == cudaSuccess) &&
               (cudaEventCreateWithFlags(&g_evB, cudaEventDisableTiming) == cudaSuccess);
    }
};
static SInit g_sinit;

// ---------------- histogram of dst (int2 vectorized; RED only, no return) ----------
__global__ void hist_kernel(const int* __restrict__ ei) {
    int e2 = (blockIdx.x * blockDim.x + threadIdx.x) * 2;
    if (e2 + 1 < N_EDGES) {
        int2 d = *reinterpret_cast<const int2*>(&ei[N_EDGES + e2]);
        atomicAdd(&g_deg[d.x], 1);
        atomicAdd(&g_deg[d.y], 1);
    } else if (e2 < N_EDGES) {
        atomicAdd(&g_deg[ei[N_EDGES + e2]], 1);
    }
}

// ---------------- scan phase 1 (also computes dinv) ----------------
__global__ __launch_bounds__(256) void scan1_kernel() {
    __shared__ int warp_tot[8];
    int tid = threadIdx.x, lane = tid & 31, wid = tid >> 5;
    int base = blockIdx.x * SCAN_TILE + tid * 4;
    int v[4]; int s = 0;
#pragma unroll
    for (int i = 0; i < 4; i++) {
        int idx = base + i;
        v[i] = (idx < N_NODES) ? g_deg[idx] : 0;
        s += v[i];
        if (idx < N_NODES) g_dinv[idx] = rsqrtf((float)(v[i] + 1));  // +1 self loop
    }
    int inc = s;
#pragma unroll
    for (int d = 1; d < 32; d <<= 1) {
        int t = __shfl_up_sync(0xFFFFFFFFu, inc, d);
        if (lane >= d) inc += t;
    }
    if (lane == 31) warp_tot[wid] = inc;
    __syncthreads();
    if (wid == 0) {
        int w = (lane < 8) ? warp_tot[lane] : 0;
#pragma unroll
        for (int d = 1; d < 8; d <<= 1) {
            int t = __shfl_up_sync(0xFFFFFFFFu, w, d);
            if (lane >= d) w += t;
        }
        if (lane < 8) warp_tot[lane] = w;
    }
    __syncthreads();
    int wex = (wid > 0) ? warp_tot[wid - 1] : 0;
    int run = wex + inc - s;
#pragma unroll
    for (int i = 0; i < 4; i++) {
        int idx = base + i;
        if (idx < N_NODES) g_off[idx] = run;
        run += v[i];
    }
    if (tid == blockDim.x - 1) g_bsums[blockIdx.x] = warp_tot[7];
}

// ---------------- scan phase 2 (shuffle-based, 196 values) ----------------
__global__ void scan2_kernel() {
    __shared__ int wsum[8];
    int t = threadIdx.x, lane = t & 31, w = t >> 5;
    int v = (t < NB_SCAN) ? g_bsums[t] : 0;
    int inc = v;
#pragma unroll
    for (int d = 1; d < 32; d <<= 1) {
        int x = __shfl_up_sync(0xFFFFFFFFu, inc, d);
        if (lane >= d) inc += x;
    }
    if (lane == 31) wsum[w] = inc;
    __syncthreads();
    if (w == 0) {
        int s = (lane < 8) ? wsum[lane] : 0;
#pragma unroll
        for (int d = 1; d < 8; d <<= 1) {
            int x = __shfl_up_sync(0xFFFFFFFFu, s, d);
            if (lane >= d) s += x;
        }
        if (lane < 8) wsum[lane] = s;
    }
    __syncthreads();
    int wex = (w > 0) ? wsum[w - 1] : 0;
    if (t < NB_SCAN) g_bsums[t] = wex + inc - v;  // exclusive
}

// ---------------- scan phase 3 (finalize g_off, init absolute cursor) ----------------
__global__ void scan3_kernel() {
    int bs = g_bsums[blockIdx.x];
    int base = blockIdx.x * SCAN_TILE + threadIdx.x * 4;
#pragma unroll
    for (int i = 0; i < 4; i++) {
        int idx = base + i;
        if (idx < N_NODES) {
            int o = g_off[idx] + bs;
            g_off[idx] = o;
            g_cur[idx] = o;
        }
    }
    if (blockIdx.x == 0 && threadIdx.x == 0) g_off[N_NODES] = N_EDGES;
}

// ---------------- CSR fill (absolute cursor, int2 vectorized) ----------------
__global__ void fill_kernel(const int* __restrict__ ei) {
    int e2 = (blockIdx.x * blockDim.x + threadIdx.x) * 2;
    if (e2 + 1 < N_EDGES) {
        int2 d = *reinterpret_cast<const int2*>(&ei[N_EDGES + e2]);
        int2 s = *reinterpret_cast<const int2*>(&ei[e2]);
        int p0 = atomicAdd(&g_cur[d.x], 1);
        g_csr[p0] = s.x;
        int p1 = atomicAdd(&g_cur[d.y], 1);
        g_csr[p1] = s.y;
    } else if (e2 < N_EDGES) {
        int d = ei[N_EDGES + e2];
        int p = atomicAdd(&g_cur[d], 1);
        g_csr[p] = ei[e2];
    }
}

// ---------------- GEMM: g_xw1 = x @ W1 (unscaled; dinv applied later) ----------------
// x loads use __ldcs (evict-first): 205MB single-use stream must not evict the
// CSR-build working set (g_deg/g_cur/g_csr) from L2 on the concurrent stream.
__global__ __launch_bounds__(128) void gemm_kernel(const float* __restrict__ x,
                                                   const float* __restrict__ W1) {
    __shared__ float ws[NUM_FEAT * DH];  // 16 KB
    __shared__ float xs[32 * 129];       // ~16.5 KB, [k][row] padded
    int tid = threadIdx.x;
    int row0 = blockIdx.x * 128;
    for (int i = tid; i < NUM_FEAT * DH; i += 128) ws[i] = W1[i];

    unsigned long long acc2[8];
#pragma unroll
    for (int c = 0; c < 8; c++) acc2[c] = 0ull;

    for (int kc = 0; kc < 8; kc++) {
        __syncthreads();
#pragma unroll
        for (int it = 0; it < 8; it++) {
            int lin = it * 128 + tid;
            int r = lin >> 3, j4 = lin & 7;
            int row = row0 + r;
            float4 v = make_float4(0.f, 0.f, 0.f, 0.f);
            if (row < N_NODES)
                v = __ldcs(reinterpret_cast<const float4*>(x) + row * 64 + kc * 8 + j4);
            int kk = j4 * 4;
            xs[(kk + 0) * 129 + r] = v.x;
            xs[(kk + 1) * 129 + r] = v.y;
            xs[(kk + 2) * 129 + r] = v.z;
            xs[(kk + 3) * 129 + r] = v.w;
        }
        __syncthreads();
        const float* wc = ws + kc * 32 * 16;
#pragma unroll
        for (int k = 0; k < 32; k++) {
            float xa = xs[k * 129 + tid];
            unsigned long long xx;
            asm("mov.b64 %0, {%1, %1};" : "=l"(xx) : "f"(xa));
            const ulonglong2* wr = reinterpret_cast<const ulonglong2*>(wc + k * 16);
            ulonglong2 w01 = wr[0], w23 = wr[1], w45 = wr[2], w67 = wr[3];
            FMA2(acc2[0], xx, w01.x);
            FMA2(acc2[1], xx, w01.y);
            FMA2(acc2[2], xx, w23.x);
            FMA2(acc2[3], xx, w23.y);
            FMA2(acc2[4], xx, w45.x);
            FMA2(acc2[5], xx, w45.y);
            FMA2(acc2[6], xx, w67.x);
            FMA2(acc2[7], xx, w67.y);
        }
    }
    int row = row0 + tid;
    if (row < N_NODES) {
        float r[16];
#pragma unroll
        for (int c = 0; c < 8; c++)
            asm("mov.b64 {%0, %1}, %2;" : "=f"(r[2 * c]), "=f"(r[2 * c + 1]) : "l"(acc2[c]));
        float4* o = reinterpret_cast<float4*>(&g_xw1[row * 16]);
        o[0] = make_float4(r[0],  r[1],  r[2],  r[3]);
        o[1] = make_float4(r[4],  r[5],  r[6],  r[7]);
        o[2] = make_float4(r[8],  r[9],  r[10], r[11]);
        o[3] = make_float4(r[12], r[13], r[14], r[15]);
    }
}

// ---------------- scale: g_xw1 *= dinv (row-wise) ----------------
__global__ __launch_bounds__(256) void scale_kernel() {
    int i = blockIdx.x * blockDim.x + threadIdx.x;   // one float4 per thread
    if (i < N_NODES * 4) {
        float dn = g_dinv[i >> 2];
        float4 v = reinterpret_cast<float4*>(g_xw1)[i];
        v.x *= dn; v.y *= dn; v.z *= dn; v.w *= dn;
        reinterpret_cast<float4*>(g_xw1)[i] = v;
    }
}

// ---------------- conv1: aggregate -> relu(+b1) -> @W2 -> dinv* -> g_xw2 ----------------
// 4 threads per node, float4 per thread. Inputs pre-scaled by dinv (self loop folds in).
__global__ __launch_bounds__(256) void conv1_kernel(const float* __restrict__ b1,
                                                    const float* __restrict__ W2) {
    __shared__ float4 w2s[64];
    __shared__ float hs[64][17];
    int tid = threadIdx.x;
    if (tid < 64) w2s[tid] = reinterpret_cast<const float4*>(W2)[tid];
    int local = tid >> 2, q = tid & 3;
    int n = blockIdx.x * 64 + local;
    float dn = 0.f;
    float hx = 0.f, hy = 0.f, hz = 0.f, hw = 0.f;
    if (n < N_NODES) {
        dn = g_dinv[n];
        const float4* tbl = reinterpret_cast<const float4*>(g_xw1);
        float4 acc = tbl[n * 4 + q];      // self loop (pre-scaled)
        int e0 = g_off[n], e1 = g_off[n + 1];
        int j = e0;
        for (; j + 1 < e1; j += 2) {
            int s0 = g_csr[j], s1 = g_csr[j + 1];
            float4 a = tbl[s0 * 4 + q];
            float4 b = tbl[s1 * 4 + q];
            acc.x += a.x + b.x; acc.y += a.y + b.y;
            acc.z += a.z + b.z; acc.w += a.w + b.w;
        }
        if (j < e1) {
            int s = g_csr[j];
            float4 a = tbl[s * 4 + q];
            acc.x += a.x; acc.y += a.y; acc.z += a.z; acc.w += a.w;
        }
        float4 bq = reinterpret_cast<const float4*>(b1)[q];
        hx = fmaxf(fmaf(acc.x, dn, bq.x), 0.f);
        hy = fmaxf(fmaf(acc.y, dn, bq.y), 0.f);
        hz = fmaxf(fmaf(acc.z, dn, bq.z), 0.f);
        hw = fmaxf(fmaf(acc.w, dn, bq.w), 0.f);
    }
    hs[local][q * 4 + 0] = hx;
    hs[local][q * 4 + 1] = hy;
    hs[local][q * 4 + 2] = hz;
    hs[local][q * 4 + 3] = hw;
    __syncthreads();
    if (n < N_NODES) {
        float4 o = make_float4(0.f, 0.f, 0.f, 0.f);
#pragma unroll
        for (int k = 0; k < 16; k++) {
            float hk = hs[local][k];
            float4 w = w2s[k * 4 + q];
            o.x = fmaf(hk, w.x, o.x);
            o.y = fmaf(hk, w.y, o.y);
            o.z = fmaf(hk, w.z, o.z);
            o.w = fmaf(hk, w.w, o.w);
        }
        reinterpret_cast<float4*>(g_xw2)[n * 4 + q] =
            make_float4(o.x * dn, o.y * dn, o.z * dn, o.w * dn);
    }
}

// ---------------- conv2: aggregate -> relu(+b2) -> g_h2 ----------------
__global__ __launch_bounds__(256) void conv2_kernel(const float* __restrict__ b2) {
    int tid = threadIdx.x;
    int local = tid >> 2, q = tid & 3;
    int n = blockIdx.x * 64 + local;
    if (n >= N_NODES) return;
    float dn = g_dinv[n];
    const float4* tbl = reinterpret_cast<const float4*>(g_xw2);
    float4 acc = tbl[n * 4 + q];
    int e0 = g_off[n], e1 = g_off[n + 1];
    int j = e0;
    for (; j + 1 < e1; j += 2) {
        int s0 = g_csr[j], s1 = g_csr[j + 1];
        float4 a = tbl[s0 * 4 + q];
        float4 b = tbl[s1 * 4 + q];
        acc.x += a.x + b.x; acc.y += a.y + b.y;
        acc.z += a.z + b.z; acc.w += a.w + b.w;
    }
    if (j < e1) {
        int s = g_csr[j];
        float4 a = tbl[s * 4 + q];
        acc.x += a.x; acc.y += a.y; acc.z += a.z; acc.w += a.w;
    }
    float4 bq = reinterpret_cast<const float4*>(b2)[q];
    float4 h;
    h.x = fmaxf(fmaf(acc.x, dn, bq.x), 0.f);
    h.y = fmaxf(fmaf(acc.y, dn, bq.y), 0.f);
    h.z = fmaxf(fmaf(acc.z, dn, bq.z), 0.f);
    h.w = fmaxf(fmaf(acc.w, dn, bq.w), 0.f);
    reinterpret_cast<float4*>(g_h2)[n * 4 + q] = h;
}

// ---------------- sort pool + fc: one block per graph (self-locating) ----------------
__global__ __launch_bounds__(256) void sortpool_kernel(const int* __restrict__ batch,
                                                       const float* __restrict__ fc_w,
                                                       const float* __restrict__ fc_b,
                                                       float* __restrict__ out) {
    __shared__ unsigned long long keys[MAXS];
    __shared__ float red[256];
    __shared__ int sh_bounds[2];
    int g = blockIdx.x;
    int tid = threadIdx.x;
    if (tid < 2) {
        int target = g + tid;
        int lo = 0, hi = N_NODES;
        while (lo < hi) {
            int mid = (lo + hi) >> 1;
            if (batch[mid] < target) lo = mid + 1; else hi = mid;
        }
        sh_bounds[tid] = lo;
    }
    __syncthreads();
    int s0 = sh_bounds[0], s1 = sh_bounds[1];
    int cnt = s1 - s0;
    if (cnt > MAXS) cnt = MAXS;
    int M = 1;
    while (M < cnt) M <<= 1;

    for (int i = tid; i < M; i += 256) {
        unsigned long long kk;
        if (i < cnt) {
            float v = g_h2[(s0 + i) * 16 + 15];       // v >= 0 post-relu
            unsigned vb = __float_as_uint(v);
            kk = ((unsigned long long)(0xFFFFFFFFu - vb) << 32) | (unsigned)i;
        } else {
            kk = 0xFFFFFFFFFFFFFFFFull;
        }
        keys[i] = kk;
    }
    __syncthreads();

    for (int len = 2; len <= M; len <<= 1) {
        for (int j = len >> 1; j > 0; j >>= 1) {
            for (int i = tid; i < M; i += 256) {
                int ixj = i ^ j;
                if (ixj > i) {
                    unsigned long long a = keys[i], b = keys[ixj];
                    bool up = ((i & len) == 0);
                    if ((a > b) == up) { keys[i] = b; keys[ixj] = a; }
                }
            }
            __syncthreads();
        }
    }

    int kl = (cnt < KTOP) ? cnt : KTOP;
    float part = 0.f;
    for (int t = tid; t < KTOP * 16; t += 256) {
        int r = t >> 4, f = t & 15;
        if (r < kl) {
            int li = (int)(keys[r] & 0xFFFFFFFFull);
            part = fmaf(g_h2[(s0 + li) * 16 + f], fc_w[t], part);
        }
    }
    red[tid] = part;
    __syncthreads();
    for (int s = 128; s > 0; s >>= 1) {
        if (tid < s) red[tid] += red[tid + s];
        __syncthreads();
    }
    if (tid == 0) out[g] = red[0] + fc_b[0];
}

// ---------------- launch ----------------
extern "C" void kernel_launch(void* const* d_in, const int* in_sizes, int n_in,
                              void* d_out, int out_size) {
    const float* x     = (const float*)d_in[0];
    const int*   ei    = (const int*)  d_in[1];
    const int*   batch = (const int*)  d_in[2];
    // d_in[3] edge_weight: unused by reference forward
    const float* W1    = (const float*)d_in[4];
    const float* b1    = (const float*)d_in[5];
    const float* W2    = (const float*)d_in[6];
    const float* b2    = (const float*)d_in[7];
    const float* fc_w  = (const float*)d_in[8];
    const float* fc_b  = (const float*)d_in[9];
    float* out = (float*)d_out;

    const int EBLK2 = (N_EDGES / 2 + 255) / 256;   // 6250
    const int CBLK  = (N_NODES + 63) / 64;         // 3125
    const int GBLK  = (N_NODES + 127) / 128;       // 1563
    const int SBLK  = (N_NODES * 4 + 255) / 256;   // 3125

    void* p_deg = nullptr;
    cudaGetSymbolAddress(&p_deg, g_deg);

    if (g_ok) {
        // fork: gemm runs on side stream concurrently with CSR build
        cudaEventRecord(g_evA, 0);
        cudaStreamWaitEvent(g_side, g_evA, 0);
        gemm_kernel<<<GBLK, 128, 0, g_side>>>(x, W1);

        cudaMemsetAsync(p_deg, 0, N_NODES * sizeof(int), 0);
        hist_kernel <<<EBLK2, 256>>>(ei);
        scan1_kernel<<<NB_SCAN, 256>>>();
        cudaEventRecord(g_evD, 0);                  // dinv ready
        scan2_kernel<<<1, 256>>>();
        scan3_kernel<<<NB_SCAN, 256>>>();
        fill_kernel <<<EBLK2, 256>>>(ei);

        cudaStreamWaitEvent(g_side, g_evD, 0);
        scale_kernel<<<SBLK, 256, 0, g_side>>>();   // xw1 *= dinv
        cudaEventRecord(g_evB, g_side);
        cudaStreamWaitEvent(0, g_evB, 0);

        conv1_kernel<<<CBLK, 256>>>(b1, W2);
        conv2_kernel<<<CBLK, 256>>>(b2);
        sortpool_kernel<<<NUM_GRAPHS, 256>>>(batch, fc_w, fc_b, out);
    } else {
        // serial fallback
        cudaMemsetAsync(p_deg, 0, N_NODES * sizeof(int), 0);
        hist_kernel <<<EBLK2, 256>>>(ei);
        scan1_kernel<<<NB_SCAN, 256>>>();
        scan2_kernel<<<1, 256>>>();
        scan3_kernel<<<NB_SCAN, 256>>>();
        fill_kernel <<<EBLK2, 256>>>(ei);
        gemm_kernel <<<GBLK, 128>>>(x, W1);
        scale_kernel<<<SBLK, 256>>>();
        conv1_kernel<<<CBLK, 256>>>(b1, W2);
        conv2_kernel<<<CBLK, 256>>>(b2);
        sortpool_kernel<<<NUM_GRAPHS, 256>>>(batch, fc_w, fc_b, out);
    }
}